// round 15
// baseline (speedup 1.0000x reference)
#include <cuda_runtime.h>
#include <math.h>

// Scratch (no cudaMalloc allowed).
__device__ float g_rinv[16384];
__device__ float g_part[16384 * 8];   // 8 partials per row

// ---------------------------------------------------------------------------
// Kernel A: PERSISTENT warp-strided row partials. One resident wave; each
// warp loops over global 4KB chunks (stride = total warps). Per-chunk body is
// bit-identical to R14 (same 8 front-batched LDG.128, shuffle reduce, fixed
// partial layout). No waves -> no wave-tail; imbalance <= 1 chunk.
// ---------------------------------------------------------------------------
__global__ void __launch_bounds__(128) partial_kernel(
    const float* __restrict__ adj, int n)
{
    const int tid    = threadIdx.x;
    const int lane   = tid & 31;
    const int warp   = tid >> 5;                   // 0..3
    const int n4     = n >> 2;                     // 2048
    const int csz    = n4 >> 3;                    // 256 float4 per chunk
    const int nchunk = n * 8;                      // total chunks
    const int stride = gridDim.x * 4;              // total warps

    for (int gchunk = blockIdx.x * 4 + warp; gchunk < nchunk; gchunk += stride) {
        const int row   = gchunk >> 3;
        const int chunk = gchunk & 7;
        const float4* r4 = reinterpret_cast<const float4*>(adj + (size_t)row * n)
                         + chunk * csz;

        float4 v[8];
        #pragma unroll
        for (int k = 0; k < 8; ++k)
            v[k] = r4[lane + k * 32];

        float4 a0 = make_float4(0.f, 0.f, 0.f, 0.f);
        float4 a1 = make_float4(0.f, 0.f, 0.f, 0.f);
        #pragma unroll
        for (int k = 0; k < 4; ++k) {
            a0.x += v[k].x;   a0.y += v[k].y;   a0.z += v[k].z;   a0.w += v[k].w;
            a1.x += v[k+4].x; a1.y += v[k+4].y; a1.z += v[k+4].z; a1.w += v[k+4].w;
        }
        float s = ((a0.x + a0.y) + (a0.z + a0.w)) + ((a1.x + a1.y) + (a1.z + a1.w));

        #pragma unroll
        for (int off = 16; off > 0; off >>= 1)
            s += __shfl_xor_sync(0xFFFFFFFFu, s, off);

        if (lane == 0)
            g_part[row * 8 + chunk] = s;
    }

    cudaTriggerProgrammaticLaunchCompletion();
}

// ---------------------------------------------------------------------------
// Kernel B: finalize (PDL). One thread per row, fixed-order sum -> r_inv.
// ---------------------------------------------------------------------------
__global__ void __launch_bounds__(256) finalize_kernel(int n)
{
    int row = blockIdx.x * blockDim.x + threadIdx.x;
    cudaGridDependencySynchronize();               // wait for partial_kernel
    if (row < n) {
        const float4* p = reinterpret_cast<const float4*>(&g_part[row * 8]);
        float4 a = p[0], b = p[1];
        float t = ((a.x + a.y) + (a.z + a.w)) + ((b.x + b.y) + (b.z + b.w));
        float rs = t + 1.0f;                       // + I diagonal
        g_rinv[row] = (rs > 0.f) ? rsqrtf(rs) : 0.f;
    }
    cudaTriggerProgrammaticLaunchCompletion();
}

// ---------------------------------------------------------------------------
// Kernel C: scale (PDL). Pre-sync register prefetch (first half) + L2
// prefetch (second half) overlap the predecessor tail. Inner math frozen.
// ---------------------------------------------------------------------------
__global__ void __launch_bounds__(256) scale_kernel(
    const float* __restrict__ adj, float* __restrict__ out, int n)
{
    const int row = (n - 1) - blockIdx.x;
    const int tid = threadIdx.x;
    const float4* arow = reinterpret_cast<const float4*>(adj + (size_t)row * n);
    float4* orow = reinterpret_cast<float4*>(out + (size_t)row * n);
    const float4* rinv4 = reinterpret_cast<const float4*>(g_rinv);
    const int n4 = n >> 2;                         // 2048

    float4 pf[4];
    #pragma unroll
    for (int k = 0; k < 4; ++k) {
        int c = tid + k * 256;
        pf[k] = __ldcs(&arow[c]);
    }
    #pragma unroll
    for (int k = 4; k < 8; ++k) {
        const float4* p = &arow[tid + k * 256];
        asm volatile("prefetch.global.L2 [%0];" :: "l"(p));
    }

    cudaGridDependencySynchronize();               // wait for r_inv
    const float ri = g_rinv[row];

    #pragma unroll
    for (int k = 0; k < 4; ++k) {
        int c = tid + k * 256;
        float4 a = pf[k];
        float4 r = rinv4[c];
        int j0 = c << 2;
        a.x += (j0 + 0 == row) ? 1.0f : 0.0f;
        a.y += (j0 + 1 == row) ? 1.0f : 0.0f;
        a.z += (j0 + 2 == row) ? 1.0f : 0.0f;
        a.w += (j0 + 3 == row) ? 1.0f : 0.0f;
        float4 o;
        o.x = a.x * ri * r.x;
        o.y = a.y * ri * r.y;
        o.z = a.z * ri * r.z;
        o.w = a.w * ri * r.w;
        __stcs(&orow[c], o);
    }

    #pragma unroll
    for (int k = 4; k < 8; ++k) {
        int c = tid + k * 256;
        if (c >= n4) break;
        float4 a = __ldcs(&arow[c]);
        float4 r = rinv4[c];
        int j0 = c << 2;
        a.x += (j0 + 0 == row) ? 1.0f : 0.0f;
        a.y += (j0 + 1 == row) ? 1.0f : 0.0f;
        a.z += (j0 + 2 == row) ? 1.0f : 0.0f;
        a.w += (j0 + 3 == row) ? 1.0f : 0.0f;
        float4 o;
        o.x = a.x * ri * r.x;
        o.y = a.y * ri * r.y;
        o.z = a.z * ri * r.z;
        o.w = a.w * ri * r.w;
        __stcs(&orow[c], o);
    }
}

extern "C" void kernel_launch(void* const* d_in, const int* in_sizes, int n_in,
                              void* d_out, int out_size)
{
    const float* adj = (const float*)d_in[0];
    float* out = (float*)d_out;

    int n = 1;
    {
        long long total = in_sizes[0];
        long long lo = 1, hi = 1 << 16;
        while (lo < hi) {
            long long mid = (lo + hi + 1) >> 1;
            if (mid * mid <= total) lo = mid; else hi = mid - 1;
        }
        n = (int)lo;
    }

    // Persistent one-wave grid for kernel A (128 thr, 32 reg -> 16 blocks/SM).
    int dev = 0, sms = 0, occ = 0;
    cudaGetDevice(&dev);
    cudaDeviceGetAttribute(&sms, cudaDevAttrMultiProcessorCount, dev);
    cudaOccupancyMaxActiveBlocksPerMultiprocessor(&occ, partial_kernel, 128, 0);
    if (occ < 1) occ = 1;
    int grid1 = sms * occ;
    int maxblocks = n * 2;                          // 8n chunks / 4 warps
    if (grid1 > maxblocks) grid1 = maxblocks;

    partial_kernel<<<grid1, 128>>>(adj, n);

    cudaLaunchAttribute attr[1];
    attr[0].id = cudaLaunchAttributeProgrammaticStreamSerialization;
    attr[0].val.programmaticStreamSerializationAllowed = 1;

    cudaLaunchConfig_t cfg = {};
    cfg.blockDim = dim3(256, 1, 1);
    cfg.dynamicSmemBytes = 0;
    cfg.stream = 0;
    cfg.attrs = attr;
    cfg.numAttrs = 1;

    cfg.gridDim = dim3((unsigned)((n + 255) / 256), 1, 1);
    cudaLaunchKernelEx(&cfg, finalize_kernel, n);

    cfg.gridDim = dim3((unsigned)n, 1, 1);
    cudaLaunchKernelEx(&cfg, scale_kernel, adj, out, n);
}

// round 16
// speedup vs baseline: 1.0042x; 1.0042x over previous
#include <cuda_runtime.h>
#include <math.h>

// Scratch (no cudaMalloc allowed).
__device__ float g_rinv[16384];
__device__ float g_part[16384 * 8];   // 8 partials per row

// ---------------------------------------------------------------------------
// Kernel A: warp-autonomous row partials, FLAT grid (no loop — the block
// scheduler provides the pipelining). 64-thread blocks: 2 warps, each owns
// one global 4KB chunk; per-warp body identical to the proven 41.1us form
// (8 front-batched LDG.128/lane, shuffle reduce, one partial store).
// ---------------------------------------------------------------------------
__global__ void __launch_bounds__(64) partial_kernel(
    const float* __restrict__ adj, int n)
{
    const int tid   = threadIdx.x;
    const int lane  = tid & 31;
    const int warp  = tid >> 5;                    // 0..1
    const int gchunk = blockIdx.x * 2 + warp;      // global chunk id
    const int row   = gchunk >> 3;
    const int chunk = gchunk & 7;
    const int n4    = n >> 2;                      // 2048
    const int csz   = n4 >> 3;                     // 256 float4 per chunk

    const float4* r4 = reinterpret_cast<const float4*>(adj + (size_t)row * n)
                     + chunk * csz;

    float4 v[8];
    #pragma unroll
    for (int k = 0; k < 8; ++k)
        v[k] = r4[lane + k * 32];

    float4 a0 = make_float4(0.f, 0.f, 0.f, 0.f);
    float4 a1 = make_float4(0.f, 0.f, 0.f, 0.f);
    #pragma unroll
    for (int k = 0; k < 4; ++k) {
        a0.x += v[k].x;   a0.y += v[k].y;   a0.z += v[k].z;   a0.w += v[k].w;
        a1.x += v[k+4].x; a1.y += v[k+4].y; a1.z += v[k+4].z; a1.w += v[k+4].w;
    }
    float s = ((a0.x + a0.y) + (a0.z + a0.w)) + ((a1.x + a1.y) + (a1.z + a1.w));

    #pragma unroll
    for (int off = 16; off > 0; off >>= 1)
        s += __shfl_xor_sync(0xFFFFFFFFu, s, off);

    if (lane == 0)
        g_part[row * 8 + chunk] = s;

    cudaTriggerProgrammaticLaunchCompletion();
}

// ---------------------------------------------------------------------------
// Kernel B: finalize (PDL). One thread per row, fixed-order sum -> r_inv.
// ---------------------------------------------------------------------------
__global__ void __launch_bounds__(256) finalize_kernel(int n)
{
    int row = blockIdx.x * blockDim.x + threadIdx.x;
    cudaGridDependencySynchronize();               // wait for partial_kernel
    if (row < n) {
        const float4* p = reinterpret_cast<const float4*>(&g_part[row * 8]);
        float4 a = p[0], b = p[1];
        float t = ((a.x + a.y) + (a.z + a.w)) + ((b.x + b.y) + (b.z + b.w));
        float rs = t + 1.0f;                       // + I diagonal
        g_rinv[row] = (rs > 0.f) ? rsqrtf(rs) : 0.f;
    }
    cudaTriggerProgrammaticLaunchCompletion();
}

// ---------------------------------------------------------------------------
// Kernel C: scale (PDL). Pre-sync register prefetch (first half) + L2
// prefetch (second half) overlap the predecessor tail. Inner math frozen
// (at the LTS mixed read+write cap for 9 rounds).
// ---------------------------------------------------------------------------
__global__ void __launch_bounds__(256) scale_kernel(
    const float* __restrict__ adj, float* __restrict__ out, int n)
{
    const int row = (n - 1) - blockIdx.x;
    const int tid = threadIdx.x;
    const float4* arow = reinterpret_cast<const float4*>(adj + (size_t)row * n);
    float4* orow = reinterpret_cast<float4*>(out + (size_t)row * n);
    const float4* rinv4 = reinterpret_cast<const float4*>(g_rinv);
    const int n4 = n >> 2;                         // 2048

    float4 pf[4];
    #pragma unroll
    for (int k = 0; k < 4; ++k) {
        int c = tid + k * 256;
        pf[k] = __ldcs(&arow[c]);
    }
    #pragma unroll
    for (int k = 4; k < 8; ++k) {
        const float4* p = &arow[tid + k * 256];
        asm volatile("prefetch.global.L2 [%0];" :: "l"(p));
    }

    cudaGridDependencySynchronize();               // wait for r_inv
    const float ri = g_rinv[row];

    #pragma unroll
    for (int k = 0; k < 4; ++k) {
        int c = tid + k * 256;
        float4 a = pf[k];
        float4 r = rinv4[c];
        int j0 = c << 2;
        a.x += (j0 + 0 == row) ? 1.0f : 0.0f;
        a.y += (j0 + 1 == row) ? 1.0f : 0.0f;
        a.z += (j0 + 2 == row) ? 1.0f : 0.0f;
        a.w += (j0 + 3 == row) ? 1.0f : 0.0f;
        float4 o;
        o.x = a.x * ri * r.x;
        o.y = a.y * ri * r.y;
        o.z = a.z * ri * r.z;
        o.w = a.w * ri * r.w;
        __stcs(&orow[c], o);
    }

    #pragma unroll
    for (int k = 4; k < 8; ++k) {
        int c = tid + k * 256;
        if (c >= n4) break;
        float4 a = __ldcs(&arow[c]);
        float4 r = rinv4[c];
        int j0 = c << 2;
        a.x += (j0 + 0 == row) ? 1.0f : 0.0f;
        a.y += (j0 + 1 == row) ? 1.0f : 0.0f;
        a.z += (j0 + 2 == row) ? 1.0f : 0.0f;
        a.w += (j0 + 3 == row) ? 1.0f : 0.0f;
        float4 o;
        o.x = a.x * ri * r.x;
        o.y = a.y * ri * r.y;
        o.z = a.z * ri * r.z;
        o.w = a.w * ri * r.w;
        __stcs(&orow[c], o);
    }
}

extern "C" void kernel_launch(void* const* d_in, const int* in_sizes, int n_in,
                              void* d_out, int out_size)
{
    const float* adj = (const float*)d_in[0];
    float* out = (float*)d_out;

    int n = 1;
    {
        long long total = in_sizes[0];
        long long lo = 1, hi = 1 << 16;
        while (lo < hi) {
            long long mid = (lo + hi + 1) >> 1;
            if (mid * mid <= total) lo = mid; else hi = mid - 1;
        }
        n = (int)lo;
    }

    partial_kernel<<<n * 4, 64>>>(adj, n);         // 4n blocks x 2 chunks = 8n chunks

    cudaLaunchAttribute attr[1];
    attr[0].id = cudaLaunchAttributeProgrammaticStreamSerialization;
    attr[0].val.programmaticStreamSerializationAllowed = 1;

    cudaLaunchConfig_t cfg = {};
    cfg.blockDim = dim3(256, 1, 1);
    cfg.dynamicSmemBytes = 0;
    cfg.stream = 0;
    cfg.attrs = attr;
    cfg.numAttrs = 1;

    cfg.gridDim = dim3((unsigned)((n + 255) / 256), 1, 1);
    cudaLaunchKernelEx(&cfg, finalize_kernel, n);

    cfg.gridDim = dim3((unsigned)n, 1, 1);
    cudaLaunchKernelEx(&cfg, scale_kernel, adj, out, n);
}